// round 12
// baseline (speedup 1.0000x reference)
#include <cuda_runtime.h>
#include <cuda_fp16.h>
#include <cstdint>

#define N_NODES 100000
#define N_EDGES 1600000
#define F_IN    256
#define F_OUT   128
#define NB_SCAN ((N_NODES + 1023) / 1024)   // 98

// Scratch
__device__ __half g_presup_h[(size_t)N_NODES * F_OUT];  // x @ W in fp16 (25.6 MB)
__device__ __half g_Wt[(size_t)F_OUT * F_IN];           // W^T in fp16 [128 n][256 k]
__device__ int    g_cnt[N_NODES];
__device__ int    g_off[N_NODES + 1];
__device__ int    g_cur[N_NODES];
__device__ int    g_bsum[128];
__device__ int2   g_edge[N_EDGES];                      // {col, val_bits}

// ============================================================================
// Kernel 1 (fused init): transpose+convert W -> Wt fp16, zero cnt
// ============================================================================
__global__ void init_kernel(const float* __restrict__ W) {
    int i = blockIdx.x * blockDim.x + threadIdx.x;
    if (i < F_IN * F_OUT) {
        int k = i >> 7;
        int n = i & 127;
        g_Wt[n * F_IN + k] = __float2half(W[i]);
    }
    if (i < N_NODES) g_cnt[i] = 0;
}

// ============================================================================
// GEMM tile body (device fn): fp16 mma.m16n8k16 + ldmatrix, one 128-row tile
// ============================================================================
#define BM 128
#define BKH 32
#define NIT2 (F_IN / BKH)   // 8
#define ASTRH 40
#define GEMM_BLOCKS   ((N_NODES + BM - 1) / BM)   // 782
#define GEMM_HALF     391
#define EDGE_BLOCKS   ((N_EDGES + 255) / 256)     // 6250

__device__ __forceinline__ void ldm_x4(uint32_t* r, uint32_t addr) {
    asm volatile("ldmatrix.sync.aligned.m8n8.x4.shared.b16 {%0,%1,%2,%3}, [%4];"
                 : "=r"(r[0]), "=r"(r[1]), "=r"(r[2]), "=r"(r[3]) : "r"(addr));
}

__device__ __forceinline__ void gemm_tile_body(int gemmBlk, const float* __restrict__ A,
                                               const __half* __restrict__ Wt,
                                               __half* __restrict__ C, int M) {
    __shared__ __half sA[2][BM][ASTRH];
    __shared__ __half sB[2][BM][ASTRH];

    const int tid  = threadIdx.x;
    const int wid  = tid >> 5;
    const int lane = tid & 31;
    const int g    = lane >> 2;
    const int t    = lane & 3;
    const int jj   = lane >> 3;
    const int rr   = lane & 7;
    const int wrow = (wid >> 1) * 32;
    const int wcol = (wid & 1) * 64;
    const int ctaRow = gemmBlk * BM;

    float acc[2][8][4];
#pragma unroll
    for (int i = 0; i < 2; i++)
#pragma unroll
        for (int j = 0; j < 8; j++)
#pragma unroll
            for (int k = 0; k < 4; k++) acc[i][j][k] = 0.0f;

    float4 areg[4];

    auto ldg_A = [&](int kt) {
#pragma unroll
        for (int i = 0; i < 4; i++) {
            int idx  = tid + i * 256;
            int arow = idx >> 3;
            int c4   = idx & 7;
            int grow = ctaRow + arow;
            if (grow >= M) grow = M - 1;
            areg[i] = *reinterpret_cast<const float4*>(&A[(size_t)grow * F_IN + kt * BKH + c4 * 4]);
        }
    };
    auto sts_A = [&](int buf) {
#pragma unroll
        for (int i = 0; i < 4; i++) {
            int idx  = tid + i * 256;
            int arow = idx >> 3;
            int c4   = idx & 7;
            __half2 h0 = __floats2half2_rn(areg[i].x, areg[i].y);
            __half2 h1 = __floats2half2_rn(areg[i].z, areg[i].w);
            uint2 v = make_uint2(*reinterpret_cast<uint32_t*>(&h0), *reinterpret_cast<uint32_t*>(&h1));
            *reinterpret_cast<uint2*>(&sA[buf][arow][c4 * 4]) = v;
        }
    };
    auto cpasync_B = [&](int kt, int buf) {
#pragma unroll
        for (int i = 0; i < 2; i++) {
            int idx = tid + i * 256;
            int n   = idx >> 2;
            int kc  = idx & 3;
            const __half* src = &Wt[(size_t)n * F_IN + kt * BKH + kc * 8];
            uint32_t dst = (uint32_t)__cvta_generic_to_shared(&sB[buf][n][kc * 8]);
            asm volatile("cp.async.cg.shared.global [%0], [%1], 16;" :: "r"(dst), "l"(src));
        }
    };

    ldg_A(0);
    cpasync_B(0, 0);
    asm volatile("cp.async.commit_group;");
    sts_A(0);

    for (int kt = 0; kt < NIT2; kt++) {
        int buf = kt & 1;
        if (kt + 1 < NIT2) {
            ldg_A(kt + 1);
            cpasync_B(kt + 1, buf ^ 1);
            asm volatile("cp.async.commit_group;");
            asm volatile("cp.async.wait_group 1;");
        } else {
            asm volatile("cp.async.wait_group 0;");
        }
        __syncthreads();

#pragma unroll
        for (int k16 = 0; k16 < BKH; k16 += 16) {
            uint32_t afr[2][4];
#pragma unroll
            for (int mt = 0; mt < 2; mt++) {
                int mrow = wrow + mt * 16 + ((jj & 1) << 3) + rr;
                int kcol = k16 + ((jj >> 1) << 3);
                ldm_x4(afr[mt], (uint32_t)__cvta_generic_to_shared(&sA[buf][mrow][kcol]));
            }
            uint32_t bfr[4][4];
#pragma unroll
            for (int ntp = 0; ntp < 4; ntp++) {
                int nrow = wcol + ntp * 16 + ((jj >> 1) << 3) + rr;
                int kcol = k16 + ((jj & 1) << 3);
                ldm_x4(bfr[ntp], (uint32_t)__cvta_generic_to_shared(&sB[buf][nrow][kcol]));
            }
#pragma unroll
            for (int mt = 0; mt < 2; mt++)
#pragma unroll
                for (int ntp = 0; ntp < 4; ntp++)
#pragma unroll
                    for (int h = 0; h < 2; h++) {
                        int nt = ntp * 2 + h;
                        asm volatile(
                            "mma.sync.aligned.m16n8k16.row.col.f32.f16.f16.f32 "
                            "{%0,%1,%2,%3}, {%4,%5,%6,%7}, {%8,%9}, {%0,%1,%2,%3};"
                            : "+f"(acc[mt][nt][0]), "+f"(acc[mt][nt][1]),
                              "+f"(acc[mt][nt][2]), "+f"(acc[mt][nt][3])
                            : "r"(afr[mt][0]), "r"(afr[mt][1]), "r"(afr[mt][2]), "r"(afr[mt][3]),
                              "r"(bfr[ntp][h * 2]), "r"(bfr[ntp][h * 2 + 1]));
                    }
        }

        if (kt + 1 < NIT2) sts_A(buf ^ 1);
        __syncthreads();
    }

    __half2* C2 = reinterpret_cast<__half2*>(C);
#pragma unroll
    for (int mt = 0; mt < 2; mt++) {
#pragma unroll
        for (int half = 0; half < 2; half++) {
            int row = ctaRow + wrow + mt * 16 + g + half * 8;
            if (row < M) {
#pragma unroll
                for (int nt = 0; nt < 8; nt++) {
                    int colb = wcol + nt * 8 + t * 2;
                    C2[(size_t)row * (F_OUT / 2) + colb / 2] =
                        __floats2half2_rn(acc[mt][nt][half * 2], acc[mt][nt][half * 2 + 1]);
                }
            }
        }
    }
}

// ============================================================================
// Fused launch 2: GEMM rows [0, 50048) || edge histogram
// ============================================================================
__global__ __launch_bounds__(256, 2) void gemm_count_fused(const float* __restrict__ A,
                                                           const __half* __restrict__ Wt,
                                                           __half* __restrict__ C,
                                                           const int* __restrict__ row) {
    if (blockIdx.x < GEMM_HALF) {
        gemm_tile_body(blockIdx.x, A, Wt, C, N_NODES);
    } else {
        int e = (blockIdx.x - GEMM_HALF) * 256 + threadIdx.x;
        if (e < N_EDGES) atomicAdd(&g_cnt[row[e]], 1);
    }
}

// ============================================================================
// Fused launch 5: GEMM rows [50048, 100000) || CSR fill
// ============================================================================
__global__ __launch_bounds__(256, 2) void gemm_fill_fused(const float* __restrict__ A,
                                                          const __half* __restrict__ Wt,
                                                          __half* __restrict__ C,
                                                          const int* __restrict__ row,
                                                          const int* __restrict__ col,
                                                          const float* __restrict__ vals) {
    if (blockIdx.x < GEMM_BLOCKS - GEMM_HALF) {
        gemm_tile_body(blockIdx.x + GEMM_HALF, A, Wt, C, N_NODES);
    } else {
        int e = (blockIdx.x - (GEMM_BLOCKS - GEMM_HALF)) * 256 + threadIdx.x;
        if (e < N_EDGES) {
            int pos = atomicAdd(&g_cur[row[e]], 1);
            g_edge[pos] = make_int2(col[e], __float_as_int(vals[e]));
        }
    }
}

// ============================================================================
// CSR scan
// ============================================================================
__global__ __launch_bounds__(1024) void scan_block_kernel() {
    __shared__ int sh[1024];
    int gid = blockIdx.x * 1024 + threadIdx.x;
    int v = (gid < N_NODES) ? g_cnt[gid] : 0;
    sh[threadIdx.x] = v;
    __syncthreads();
#pragma unroll
    for (int d = 1; d < 1024; d <<= 1) {
        int t = (threadIdx.x >= d) ? sh[threadIdx.x - d] : 0;
        __syncthreads();
        sh[threadIdx.x] += t;
        __syncthreads();
    }
    if (gid < N_NODES) g_off[gid] = sh[threadIdx.x] - v;
    if (threadIdx.x == 1023) g_bsum[blockIdx.x] = sh[1023];
}

__global__ __launch_bounds__(256) void add_base2_kernel() {
    __shared__ int sh_base;
    int blk0 = blockIdx.x * 256;
    int chunk = blk0 >> 10;

    if (threadIdx.x < 32) {
        int sum = 0;
        for (int j = threadIdx.x; j < chunk; j += 32) sum += g_bsum[j];
#pragma unroll
        for (int d = 16; d > 0; d >>= 1) sum += __shfl_down_sync(0xFFFFFFFF, sum, d);
        if (threadIdx.x == 0) sh_base = sum;
    }
    __syncthreads();

    int i = blk0 + threadIdx.x;
    if (i < N_NODES) {
        int o = g_off[i] + sh_base;
        g_off[i] = o;
        g_cur[i] = o;
    }
    if (i == 0) g_off[N_NODES] = N_EDGES;
}

// ============================================================================
// Gather: warp per node, 4-way edge unroll; fp16 feats, fp32 accumulate;
// fused bias + relu + store
// ============================================================================
__device__ __forceinline__ void acc_edge(float4& acc, const uint2* pre2, int2 ed, int lane) {
    float v = __int_as_float(ed.y);
    uint2 r = pre2[(size_t)ed.x * 32 + lane];
    float2 a0 = __half22float2(*reinterpret_cast<__half2*>(&r.x));
    float2 a1 = __half22float2(*reinterpret_cast<__half2*>(&r.y));
    acc.x += v * a0.x;
    acc.y += v * a0.y;
    acc.z += v * a1.x;
    acc.w += v * a1.y;
}

__global__ __launch_bounds__(256) void gather_kernel(const __half* __restrict__ pre,
                                                     const float* __restrict__ b,
                                                     float* __restrict__ out) {
    int n = (blockIdx.x * blockDim.x + threadIdx.x) >> 5;
    int lane = threadIdx.x & 31;
    if (n >= N_NODES) return;

    int s = g_off[n];
    int e = g_off[n + 1];

    const uint2* pre2 = reinterpret_cast<const uint2*>(pre);
    float4 acc = make_float4(0.f, 0.f, 0.f, 0.f);

    int i = s;
    for (; i + 3 < e; i += 4) {
        int2 e0 = g_edge[i], e1 = g_edge[i + 1], e2 = g_edge[i + 2], e3 = g_edge[i + 3];
        float v0 = __int_as_float(e0.y), v1 = __int_as_float(e1.y);
        float v2 = __int_as_float(e2.y), v3 = __int_as_float(e3.y);
        uint2 r0 = pre2[(size_t)e0.x * 32 + lane];
        uint2 r1 = pre2[(size_t)e1.x * 32 + lane];
        uint2 r2 = pre2[(size_t)e2.x * 32 + lane];
        uint2 r3 = pre2[(size_t)e3.x * 32 + lane];
        float2 a0 = __half22float2(*reinterpret_cast<__half2*>(&r0.x));
        float2 a1 = __half22float2(*reinterpret_cast<__half2*>(&r0.y));
        float2 b0 = __half22float2(*reinterpret_cast<__half2*>(&r1.x));
        float2 b1 = __half22float2(*reinterpret_cast<__half2*>(&r1.y));
        float2 c0 = __half22float2(*reinterpret_cast<__half2*>(&r2.x));
        float2 c1 = __half22float2(*reinterpret_cast<__half2*>(&r2.y));
        float2 d0 = __half22float2(*reinterpret_cast<__half2*>(&r3.x));
        float2 d1 = __half22float2(*reinterpret_cast<__half2*>(&r3.y));
        acc.x += v0 * a0.x + v1 * b0.x + v2 * c0.x + v3 * d0.x;
        acc.y += v0 * a0.y + v1 * b0.y + v2 * c0.y + v3 * d0.y;
        acc.z += v0 * a1.x + v1 * b1.x + v2 * c1.x + v3 * d1.x;
        acc.w += v0 * a1.y + v1 * b1.y + v2 * c1.y + v3 * d1.y;
    }
    for (; i < e; i++) acc_edge(acc, pre2, g_edge[i], lane);

    float4 bb = reinterpret_cast<const float4*>(b)[lane];
    acc.x = fmaxf(acc.x + bb.x, 0.f);
    acc.y = fmaxf(acc.y + bb.y, 0.f);
    acc.z = fmaxf(acc.z + bb.z, 0.f);
    acc.w = fmaxf(acc.w + bb.w, 0.f);
    reinterpret_cast<float4*>(out)[(size_t)n * 32 + lane] = acc;
}

// ============================================================================
// Launch.  Inputs: x[N,256] f32, W[256,128] f32, b[128] f32,
//                  vals[E] f32, row[E] i32, col[E] i32.  Output [N,128] f32.
// Timeline: GEMM halves overlap the two expensive CSR-build stages.
// ============================================================================
extern "C" void kernel_launch(void* const* d_in, const int* in_sizes, int n_in,
                              void* d_out, int out_size) {
    const float* x    = (const float*)d_in[0];
    const float* W    = (const float*)d_in[1];
    const float* b    = (const float*)d_in[2];
    const float* vals = (const float*)d_in[3];
    const int*   row  = (const int*)  d_in[4];
    const int*   col  = (const int*)  d_in[5];
    float* out = (float*)d_out;

    __half* presup; cudaGetSymbolAddress((void**)&presup, g_presup_h);
    __half* Wt;     cudaGetSymbolAddress((void**)&Wt, g_Wt);

    init_kernel<<<(N_NODES + 255) / 256, 256>>>(W);                         // 1
    gemm_count_fused<<<GEMM_HALF + EDGE_BLOCKS, 256>>>(x, Wt, presup, row); // 2
    scan_block_kernel<<<NB_SCAN, 1024>>>();                                 // 3
    add_base2_kernel<<<(N_NODES + 255) / 256, 256>>>();                     // 4
    gemm_fill_fused<<<(GEMM_BLOCKS - GEMM_HALF) + EDGE_BLOCKS, 256>>>(x, Wt, presup, row, col, vals); // 5
    gather_kernel<<<(int)(((long long)N_NODES * 32 + 255) / 256), 256>>>(presup, b, out); // 6
}

// round 13
// speedup vs baseline: 1.1619x; 1.1619x over previous
#include <cuda_runtime.h>
#include <cuda_fp16.h>
#include <cstdint>

#define N_NODES 100000
#define N_EDGES 1600000
#define F_IN    256
#define F_OUT   128
#define NB_SCAN ((N_NODES + 1023) / 1024)   // 98

// Scratch
__device__ __half g_presup_h[(size_t)N_NODES * F_OUT];  // x @ W in fp16 (25.6 MB)
__device__ __half g_Wt[(size_t)F_OUT * F_IN];           // W^T in fp16 [128 n][256 k]
__device__ int    g_cnt[N_NODES];
__device__ int    g_off[N_NODES + 1];
__device__ int    g_cur[N_NODES];
__device__ int    g_bsum[128];
__device__ int2   g_edge[N_EDGES];                      // {col, val_bits}

// ============================================================================
// Kernel: fused init — transpose+convert W -> Wt fp16, zero cnt
// ============================================================================
__global__ void init_kernel(const float* __restrict__ W) {
    int i = blockIdx.x * blockDim.x + threadIdx.x;
    if (i < F_IN * F_OUT) {
        int k = i >> 7;
        int n = i & 127;
        g_Wt[n * F_IN + k] = __float2half(W[i]);
    }
    if (i < N_NODES) g_cnt[i] = 0;
}

// ============================================================================
// GEMM: fp16 mma.sync.m16n8k16 + ldmatrix (identical to R11 passing version)
// ============================================================================
#define BM 128
#define BKH 32
#define NIT2 (F_IN / BKH)   // 8
#define ASTRH 40

__device__ __forceinline__ void ldm_x4(uint32_t* r, uint32_t addr) {
    asm volatile("ldmatrix.sync.aligned.m8n8.x4.shared.b16 {%0,%1,%2,%3}, [%4];"
                 : "=r"(r[0]), "=r"(r[1]), "=r"(r[2]), "=r"(r[3]) : "r"(addr));
}

__global__ __launch_bounds__(256, 2) void gemm_h_kernel(const float* __restrict__ A,
                                                        const __half* __restrict__ Wt,
                                                        __half* __restrict__ C,
                                                        int M) {
    __shared__ __half sA[2][BM][ASTRH];
    __shared__ __half sB[2][BM][ASTRH];

    const int tid  = threadIdx.x;
    const int wid  = tid >> 5;
    const int lane = tid & 31;
    const int g    = lane >> 2;
    const int t    = lane & 3;
    const int jj   = lane >> 3;
    const int rr   = lane & 7;
    const int wrow = (wid >> 1) * 32;
    const int wcol = (wid & 1) * 64;
    const int ctaRow = blockIdx.x * BM;

    float acc[2][8][4];
#pragma unroll
    for (int i = 0; i < 2; i++)
#pragma unroll
        for (int j = 0; j < 8; j++)
#pragma unroll
            for (int k = 0; k < 4; k++) acc[i][j][k] = 0.0f;

    float4 areg[4];

    auto ldg_A = [&](int kt) {
#pragma unroll
        for (int i = 0; i < 4; i++) {
            int idx  = tid + i * 256;
            int arow = idx >> 3;
            int c4   = idx & 7;
            int grow = ctaRow + arow;
            if (grow >= M) grow = M - 1;
            areg[i] = *reinterpret_cast<const float4*>(&A[(size_t)grow * F_IN + kt * BKH + c4 * 4]);
        }
    };
    auto sts_A = [&](int buf) {
#pragma unroll
        for (int i = 0; i < 4; i++) {
            int idx  = tid + i * 256;
            int arow = idx >> 3;
            int c4   = idx & 7;
            __half2 h0 = __floats2half2_rn(areg[i].x, areg[i].y);
            __half2 h1 = __floats2half2_rn(areg[i].z, areg[i].w);
            uint2 v = make_uint2(*reinterpret_cast<uint32_t*>(&h0), *reinterpret_cast<uint32_t*>(&h1));
            *reinterpret_cast<uint2*>(&sA[buf][arow][c4 * 4]) = v;
        }
    };
    auto cpasync_B = [&](int kt, int buf) {
#pragma unroll
        for (int i = 0; i < 2; i++) {
            int idx = tid + i * 256;
            int n   = idx >> 2;
            int kc  = idx & 3;
            const __half* src = &Wt[(size_t)n * F_IN + kt * BKH + kc * 8];
            uint32_t dst = (uint32_t)__cvta_generic_to_shared(&sB[buf][n][kc * 8]);
            asm volatile("cp.async.cg.shared.global [%0], [%1], 16;" :: "r"(dst), "l"(src));
        }
    };

    ldg_A(0);
    cpasync_B(0, 0);
    asm volatile("cp.async.commit_group;");
    sts_A(0);

    for (int kt = 0; kt < NIT2; kt++) {
        int buf = kt & 1;
        if (kt + 1 < NIT2) {
            ldg_A(kt + 1);
            cpasync_B(kt + 1, buf ^ 1);
            asm volatile("cp.async.commit_group;");
            asm volatile("cp.async.wait_group 1;");
        } else {
            asm volatile("cp.async.wait_group 0;");
        }
        __syncthreads();

#pragma unroll
        for (int k16 = 0; k16 < BKH; k16 += 16) {
            uint32_t afr[2][4];
#pragma unroll
            for (int mt = 0; mt < 2; mt++) {
                int mrow = wrow + mt * 16 + ((jj & 1) << 3) + rr;
                int kcol = k16 + ((jj >> 1) << 3);
                ldm_x4(afr[mt], (uint32_t)__cvta_generic_to_shared(&sA[buf][mrow][kcol]));
            }
            uint32_t bfr[4][4];
#pragma unroll
            for (int ntp = 0; ntp < 4; ntp++) {
                int nrow = wcol + ntp * 16 + ((jj >> 1) << 3) + rr;
                int kcol = k16 + ((jj & 1) << 3);
                ldm_x4(bfr[ntp], (uint32_t)__cvta_generic_to_shared(&sB[buf][nrow][kcol]));
            }
#pragma unroll
            for (int mt = 0; mt < 2; mt++)
#pragma unroll
                for (int ntp = 0; ntp < 4; ntp++)
#pragma unroll
                    for (int h = 0; h < 2; h++) {
                        int nt = ntp * 2 + h;
                        asm volatile(
                            "mma.sync.aligned.m16n8k16.row.col.f32.f16.f16.f32 "
                            "{%0,%1,%2,%3}, {%4,%5,%6,%7}, {%8,%9}, {%0,%1,%2,%3};"
                            : "+f"(acc[mt][nt][0]), "+f"(acc[mt][nt][1]),
                              "+f"(acc[mt][nt][2]), "+f"(acc[mt][nt][3])
                            : "r"(afr[mt][0]), "r"(afr[mt][1]), "r"(afr[mt][2]), "r"(afr[mt][3]),
                              "r"(bfr[ntp][h * 2]), "r"(bfr[ntp][h * 2 + 1]));
                    }
        }

        if (kt + 1 < NIT2) sts_A(buf ^ 1);
        __syncthreads();
    }

    __half2* C2 = reinterpret_cast<__half2*>(C);
#pragma unroll
    for (int mt = 0; mt < 2; mt++) {
#pragma unroll
        for (int half = 0; half < 2; half++) {
            int row = ctaRow + wrow + mt * 16 + g + half * 8;
            if (row < M) {
#pragma unroll
                for (int nt = 0; nt < 8; nt++) {
                    int colb = wcol + nt * 8 + t * 2;
                    C2[(size_t)row * (F_OUT / 2) + colb / 2] =
                        __floats2half2_rn(acc[mt][nt][half * 2], acc[mt][nt][half * 2 + 1]);
                }
            }
        }
    }
}

// ============================================================================
// CSR build (dedicated lightweight kernels — own small footprints)
// ============================================================================
__global__ void count_kernel(const int* __restrict__ row) {
    int e = blockIdx.x * blockDim.x + threadIdx.x;
    if (e < N_EDGES) atomicAdd(&g_cnt[row[e]], 1);
}

__global__ __launch_bounds__(1024) void scan_block_kernel() {
    __shared__ int sh[1024];
    int gid = blockIdx.x * 1024 + threadIdx.x;
    int v = (gid < N_NODES) ? g_cnt[gid] : 0;
    sh[threadIdx.x] = v;
    __syncthreads();
#pragma unroll
    for (int d = 1; d < 1024; d <<= 1) {
        int t = (threadIdx.x >= d) ? sh[threadIdx.x - d] : 0;
        __syncthreads();
        sh[threadIdx.x] += t;
        __syncthreads();
    }
    if (gid < N_NODES) g_off[gid] = sh[threadIdx.x] - v;
    if (threadIdx.x == 1023) g_bsum[blockIdx.x] = sh[1023];
}

__global__ __launch_bounds__(256) void add_base2_kernel() {
    __shared__ int sh_base;
    int blk0 = blockIdx.x * 256;
    int chunk = blk0 >> 10;

    if (threadIdx.x < 32) {
        int sum = 0;
        for (int j = threadIdx.x; j < chunk; j += 32) sum += g_bsum[j];
#pragma unroll
        for (int d = 16; d > 0; d >>= 1) sum += __shfl_down_sync(0xFFFFFFFF, sum, d);
        if (threadIdx.x == 0) sh_base = sum;
    }
    __syncthreads();

    int i = blk0 + threadIdx.x;
    if (i < N_NODES) {
        int o = g_off[i] + sh_base;
        g_off[i] = o;
        g_cur[i] = o;
    }
    if (i == 0) g_off[N_NODES] = N_EDGES;
}

__global__ void fill_kernel(const int* __restrict__ row, const int* __restrict__ col,
                            const float* __restrict__ vals) {
    int e = blockIdx.x * blockDim.x + threadIdx.x;
    if (e < N_EDGES) {
        int pos = atomicAdd(&g_cur[row[e]], 1);
        g_edge[pos] = make_int2(col[e], __float_as_int(vals[e]));
    }
}

// ============================================================================
// Gather: warp per node, 4-way edge unroll; fp16 feats, fp32 accumulate;
// fused bias + relu + store
// ============================================================================
__device__ __forceinline__ void acc_edge(float4& acc, const uint2* pre2, int2 ed, int lane) {
    float v = __int_as_float(ed.y);
    uint2 r = pre2[(size_t)ed.x * 32 + lane];
    float2 a0 = __half22float2(*reinterpret_cast<__half2*>(&r.x));
    float2 a1 = __half22float2(*reinterpret_cast<__half2*>(&r.y));
    acc.x += v * a0.x;
    acc.y += v * a0.y;
    acc.z += v * a1.x;
    acc.w += v * a1.y;
}

__global__ __launch_bounds__(256) void gather_kernel(const __half* __restrict__ pre,
                                                     const float* __restrict__ b,
                                                     float* __restrict__ out) {
    int n = (blockIdx.x * blockDim.x + threadIdx.x) >> 5;
    int lane = threadIdx.x & 31;
    if (n >= N_NODES) return;

    int s = g_off[n];
    int e = g_off[n + 1];

    const uint2* pre2 = reinterpret_cast<const uint2*>(pre);
    float4 acc = make_float4(0.f, 0.f, 0.f, 0.f);

    int i = s;
    for (; i + 3 < e; i += 4) {
        int2 e0 = g_edge[i], e1 = g_edge[i + 1], e2 = g_edge[i + 2], e3 = g_edge[i + 3];
        float v0 = __int_as_float(e0.y), v1 = __int_as_float(e1.y);
        float v2 = __int_as_float(e2.y), v3 = __int_as_float(e3.y);
        uint2 r0 = pre2[(size_t)e0.x * 32 + lane];
        uint2 r1 = pre2[(size_t)e1.x * 32 + lane];
        uint2 r2 = pre2[(size_t)e2.x * 32 + lane];
        uint2 r3 = pre2[(size_t)e3.x * 32 + lane];
        float2 a0 = __half22float2(*reinterpret_cast<__half2*>(&r0.x));
        float2 a1 = __half22float2(*reinterpret_cast<__half2*>(&r0.y));
        float2 b0 = __half22float2(*reinterpret_cast<__half2*>(&r1.x));
        float2 b1 = __half22float2(*reinterpret_cast<__half2*>(&r1.y));
        float2 c0 = __half22float2(*reinterpret_cast<__half2*>(&r2.x));
        float2 c1 = __half22float2(*reinterpret_cast<__half2*>(&r2.y));
        float2 d0 = __half22float2(*reinterpret_cast<__half2*>(&r3.x));
        float2 d1 = __half22float2(*reinterpret_cast<__half2*>(&r3.y));
        acc.x += v0 * a0.x + v1 * b0.x + v2 * c0.x + v3 * d0.x;
        acc.y += v0 * a0.y + v1 * b0.y + v2 * c0.y + v3 * d0.y;
        acc.z += v0 * a1.x + v1 * b1.x + v2 * c1.x + v3 * d1.x;
        acc.w += v0 * a1.y + v1 * b1.y + v2 * c1.y + v3 * d1.y;
    }
    for (; i < e; i++) acc_edge(acc, pre2, g_edge[i], lane);

    float4 bb = reinterpret_cast<const float4*>(b)[lane];
    acc.x = fmaxf(acc.x + bb.x, 0.f);
    acc.y = fmaxf(acc.y + bb.y, 0.f);
    acc.z = fmaxf(acc.z + bb.z, 0.f);
    acc.w = fmaxf(acc.w + bb.w, 0.f);
    reinterpret_cast<float4*>(out)[(size_t)n * 32 + lane] = acc;
}

// ============================================================================
// Launch.  Inputs: x[N,256] f32, W[256,128] f32, b[128] f32,
//                  vals[E] f32, row[E] i32, col[E] i32.  Output [N,128] f32.
// Graph fork: GEMM on side stream runs concurrently with the CSR-build chain.
// Streams/events created once on first (uncaptured) call; identical DAG every call.
// ============================================================================
extern "C" void kernel_launch(void* const* d_in, const int* in_sizes, int n_in,
                              void* d_out, int out_size) {
    const float* x    = (const float*)d_in[0];
    const float* W    = (const float*)d_in[1];
    const float* b    = (const float*)d_in[2];
    const float* vals = (const float*)d_in[3];
    const int*   row  = (const int*)  d_in[4];
    const int*   col  = (const int*)  d_in[5];
    float* out = (float*)d_out;

    __half* presup; cudaGetSymbolAddress((void**)&presup, g_presup_h);
    __half* Wt;     cudaGetSymbolAddress((void**)&Wt, g_Wt);

    static cudaStream_t s1 = nullptr;
    static cudaEvent_t  evFork = nullptr, evJoin = nullptr;
    if (s1 == nullptr) {
        cudaStreamCreateWithFlags(&s1, cudaStreamNonBlocking);
        cudaEventCreateWithFlags(&evFork, cudaEventDisableTiming);
        cudaEventCreateWithFlags(&evJoin, cudaEventDisableTiming);
    }

    // 1. init (Wt + cnt=0) on main stream
    init_kernel<<<(N_NODES + 255) / 256, 256>>>(W);

    // fork: side stream waits for init
    cudaEventRecord(evFork, 0);
    cudaStreamWaitEvent(s1, evFork, 0);

    // branch A (s1): GEMM
    gemm_h_kernel<<<(N_NODES + BM - 1) / BM, 256, 0, s1>>>(x, Wt, presup, N_NODES);
    cudaEventRecord(evJoin, s1);

    // branch B (main): CSR build
    count_kernel<<<(N_EDGES + 255) / 256, 256>>>(row);
    scan_block_kernel<<<NB_SCAN, 1024>>>();
    add_base2_kernel<<<(N_NODES + 255) / 256, 256>>>();
    fill_kernel<<<(N_EDGES + 255) / 256, 256>>>(row, col, vals);

    // join: gather needs presup (A) and edges (B)
    cudaStreamWaitEvent(0, evJoin, 0);
    gather_kernel<<<(int)(((long long)N_NODES * 32 + 255) / 256), 256>>>(presup, b, out);
}